// round 3
// baseline (speedup 1.0000x reference)
#include <cuda_runtime.h>
#include <cstdint>

// ============================================================================
// WaveletKAN: out[128,4096] = x @ W^T + wavelet(x) + bias
//   Kernel 1: per-image Haar DWT(4 levels) + quantile prune + IDWT -> g_wav
//   Kernel 2: tf32 mma.sync GEMM (BM64 x BN64 x BK32, 3-stage cp.async,
//             swizzled smem + ldmatrix), epilogue adds bias + g_wav.
// ============================================================================

#define BM 64
#define BN 64
#define BK 32
#define STAGES 3
#define KDIM 4096
#define NT (KDIM / BK)          // 128 k-tiles

__device__ float g_wav[128 * 4096];   // wavelet_out scratch (2 MB)

// ---------------------------------------------------------------------------
// Wavelet kernel: one block per batch image (64x64), 128 threads.
// ---------------------------------------------------------------------------
__global__ void __launch_bounds__(128) wavelet_kernel(
    const float* __restrict__ x, const float* __restrict__ sf)
{
    // levels storage with pitch hh+1 (odd pitch -> conflict-free row access)
    // l0: 4*32*33=4224, l1: 4*16*17=1088, l2: 4*8*9=288, l3: 4*4*5=80 -> 5680
    __shared__ float A[4096];     // 64x64 image / final reconstruction
    __shared__ float Wb0[1024];
    __shared__ float Wb1[1024];
    __shared__ float lev[5680];

    const int b   = blockIdx.x;
    const int tid = threadIdx.x;
    const float* xb = x + (size_t)b * 4096;

    for (int i = tid; i < 4096; i += 128) A[i] = xb[i];
    __syncthreads();

    const int loff[4] = {0, 4224, 5312, 5600};

    float* cur = A;
    float* nxt = Wb0;

    // ---------------- forward: DWT + scale + prune ----------------
    for (int l = 0; l < 4; ++l) {
        const int h = 64 >> l, hh = h >> 1, p = hh + 1;
        const float s0 = sf[l * 4 + 0], s1 = sf[l * 4 + 1];
        const float s2 = sf[l * 4 + 2], s3 = sf[l * 4 + 3];
        float* L = lev + loff[l];
        const int n = hh * hh;

        for (int idx = tid; idx < n; idx += 128) {
            int i = idx / hh, jj = idx - i * hh;
            float a  = cur[(2 * i)     * h + 2 * jj];
            float bb = cur[(2 * i)     * h + 2 * jj + 1];
            float c  = cur[(2 * i + 1) * h + 2 * jj];
            float d  = cur[(2 * i + 1) * h + 2 * jj + 1];
            float ca = (a + bb + c + d) * 0.5f;
            float ch = (a - bb + c - d) * 0.5f;
            float cv = (a + bb - c - d) * 0.5f;
            float cd = (a - bb - c + d) * 0.5f;
            nxt[idx] = ca;  // raw cA feeds next level
            L[(0 * hh + i) * p + jj] = ca * s0;
            L[(1 * hh + i) * p + jj] = ch * s1;
            L[(2 * hh + i) * p + jj] = cv * s2;
            L[(3 * hh + i) * p + jj] = cd * s3;
        }
        __syncthreads();

        // prune: per-row 0.4 quantile (linear interpolation), rows = 4*hh <= 128
        if (tid < 4 * hh) {
            float* row = L + tid * p;
            float buf[32];
            for (int t = 0; t < hh; ++t) buf[t] = fabsf(row[t]);
            for (int t = 1; t < hh; ++t) {       // insertion sort
                float key = buf[t];
                int u = t - 1;
                while (u >= 0 && buf[u] > key) { buf[u + 1] = buf[u]; --u; }
                buf[u + 1] = key;
            }
            float pos  = 0.4f * (float)(hh - 1);
            int   lo2  = (int)pos;
            float frac = pos - (float)lo2;
            float thr  = buf[lo2] + frac * (buf[lo2 + 1] - buf[lo2]);
            for (int t = 0; t < hh; ++t)
                if (fabsf(row[t]) <= thr) row[t] = 0.0f;
        }
        __syncthreads();

        float* newcur = nxt;
        nxt = (newcur == Wb0) ? Wb1 : Wb0;
        cur = newcur;
    }

    // ---------------- reconstruction ----------------
    // rec starts from pruned cA of level 3 (4x4, pitch 5)
    if (tid < 16) {
        int i = tid >> 2, jj = tid & 3;
        Wb0[tid] = lev[loff[3] + i * 5 + jj];
    }
    __syncthreads();

    cur = Wb0;
    for (int l = 3; l >= 0; --l) {
        const int hh = 32 >> l, p = hh + 1, h2 = hh * 2;
        const int n = hh * hh;
        float* L = lev + loff[l];
        float* outb = (l == 0) ? A : ((cur == Wb0) ? Wb1 : Wb0);

        for (int idx = tid; idx < n; idx += 128) {
            int i = idx / hh, jj = idx - i * hh;
            float ca = cur[idx];
            float ch = L[(1 * hh + i) * p + jj];
            float cv = L[(2 * hh + i) * p + jj];
            float cd = L[(3 * hh + i) * p + jj];
            float a  = (ca + ch + cv + cd) * 0.5f;
            float bb = (ca - ch + cv - cd) * 0.5f;
            float c  = (ca + ch - cv - cd) * 0.5f;
            float d  = (ca - ch - cv + cd) * 0.5f;
            outb[(2 * i)     * h2 + 2 * jj]     = a;
            outb[(2 * i)     * h2 + 2 * jj + 1] = bb;
            outb[(2 * i + 1) * h2 + 2 * jj]     = c;
            outb[(2 * i + 1) * h2 + 2 * jj + 1] = d;
        }
        __syncthreads();
        cur = outb;
    }

    float* wout = g_wav + (size_t)b * 4096;
    for (int i = tid; i < 4096; i += 128) wout[i] = A[i];
}

// ---------------------------------------------------------------------------
// tf32 GEMM
// ---------------------------------------------------------------------------
__device__ __forceinline__ void cp_async16(uint32_t dst, const void* src) {
    asm volatile("cp.async.cg.shared.global [%0], [%1], 16;\n" :: "r"(dst), "l"(src));
}
__device__ __forceinline__ void ldsm_x4(uint32_t* d, uint32_t addr) {
    asm volatile("ldmatrix.sync.aligned.m8n8.x4.shared.b16 {%0,%1,%2,%3}, [%4];"
        : "=r"(d[0]), "=r"(d[1]), "=r"(d[2]), "=r"(d[3]) : "r"(addr));
}
__device__ __forceinline__ uint32_t f2tf(uint32_t v) {
    uint32_t r;
    asm("cvt.rna.tf32.f32 %0, %1;" : "=r"(r) : "f"(__uint_as_float(v)));
    return r;
}
__device__ __forceinline__ void mma_tf32(float* c, const uint32_t* a,
                                         uint32_t b0, uint32_t b1) {
    asm("mma.sync.aligned.m16n8k8.row.col.f32.tf32.tf32.f32 "
        "{%0,%1,%2,%3}, {%4,%5,%6,%7}, {%8,%9}, {%0,%1,%2,%3};"
        : "+f"(c[0]), "+f"(c[1]), "+f"(c[2]), "+f"(c[3])
        : "r"(a[0]), "r"(a[1]), "r"(a[2]), "r"(a[3]), "r"(b0), "r"(b1));
}

__global__ void __launch_bounds__(128) gemm_tf32_kernel(
    const float* __restrict__ X, const float* __restrict__ Wt,
    const float* __restrict__ bias, float* __restrict__ out)
{
    extern __shared__ float smem[];   // A: STAGES*2048 floats, then B: STAGES*2048

    const int tid  = threadIdx.x;
    const int lane = tid & 31, warp = tid >> 5;
    const int wm = warp >> 1, wn = warp & 1;   // 2x2 warp grid, 32x32 warp tile
    const int nb = blockIdx.x, mb = blockIdx.y;

    const float* Ag = X  + (size_t)mb * 64 * KDIM;
    const float* Bg = Wt + (size_t)nb * 64 * KDIM;

    const uint32_t sBase = (uint32_t)__cvta_generic_to_shared(smem);
    const uint32_t bOfs  = STAGES * 2048u * 4u;   // B region byte offset (24576)

    // cp.async per-thread chunks: 4 for A + 4 for B per tile.
    // chunk id = tid + 128*i; row = id>>3 (0..63); c = id&7 (16B chunk in row).
    // store with XOR swizzle: chunk position = c ^ (row & 7)
    int rowArr[4], cArr[4];
    uint32_t stOff[4];
#pragma unroll
    for (int i = 0; i < 4; ++i) {
        int id  = tid + 128 * i;
        int row = id >> 3, c = id & 7;
        rowArr[i] = row; cArr[i] = c;
        stOff[i]  = (uint32_t)((row * 32 + ((c ^ (row & 7)) << 2)) << 2);
    }

    float acc[2][4][4];
#pragma unroll
    for (int a1 = 0; a1 < 2; ++a1)
#pragma unroll
        for (int a2 = 0; a2 < 4; ++a2)
#pragma unroll
            for (int a3 = 0; a3 < 4; ++a3) acc[a1][a2][a3] = 0.0f;

    // ldmatrix lane geometry: matrix j = lane>>3, row-in-matrix r = lane&7
    const int j = lane >> 3, r = lane & 7;
    const int cja = (j >> 1);   // A: j0,1 -> k-chunk 2s ; j2,3 -> 2s+1
    const int cjb = (j & 1);    // B: j0,2 -> k-chunk 2s ; j1,3 -> 2s+1
    const uint32_t aRow0 = (uint32_t)(((wm * 32 + (j & 1) * 8 + r) * 32) << 2);
    const uint32_t aRow1 = aRow0 + (uint32_t)((16 * 32) << 2);
    const uint32_t bRow0 = (uint32_t)(((wn * 32 + (j >> 1) * 8 + r) * 32) << 2);
    const uint32_t bRow1 = bRow0 + (uint32_t)((16 * 32) << 2);

#define ISSUE(kt, stg) {                                                       \
        uint32_t sa = sBase + (uint32_t)(stg) * 8192u;                          \
        const float* pa = Ag + (size_t)(kt) * 32;                               \
        const float* pb = Bg + (size_t)(kt) * 32;                               \
        _Pragma("unroll")                                                       \
        for (int i = 0; i < 4; ++i) {                                           \
            cp_async16(sa + stOff[i],        pa + (size_t)rowArr[i] * KDIM + cArr[i] * 4); \
            cp_async16(sa + bOfs + stOff[i], pb + (size_t)rowArr[i] * KDIM + cArr[i] * 4); \
        } }

#define COMPUTE(stg) {                                                          \
        uint32_t aB = sBase + (uint32_t)(stg) * 8192u;                          \
        uint32_t bB = aB + bOfs;                                                \
        _Pragma("unroll")                                                       \
        for (int s = 0; s < 4; ++s) {                                           \
            uint32_t av[2][4], bv[2][4];                                        \
            uint32_t ca = (uint32_t)((((2 * s + cja) ^ r)) << 4);               \
            uint32_t cb = (uint32_t)((((2 * s + cjb) ^ r)) << 4);               \
            ldsm_x4(av[0], aB + aRow0 + ca);                                    \
            ldsm_x4(av[1], aB + aRow1 + ca);                                    \
            ldsm_x4(bv[0], bB + bRow0 + cb);                                    \
            ldsm_x4(bv[1], bB + bRow1 + cb);                                    \
            _Pragma("unroll")                                                   \
            for (int q = 0; q < 4; ++q) {                                       \
                av[0][q] = f2tf(av[0][q]); av[1][q] = f2tf(av[1][q]);           \
                bv[0][q] = f2tf(bv[0][q]); bv[1][q] = f2tf(bv[1][q]);           \
            }                                                                   \
            _Pragma("unroll")                                                   \
            for (int mt = 0; mt < 2; ++mt) {                                    \
                mma_tf32(acc[mt][0], av[mt], bv[0][0], bv[0][1]);               \
                mma_tf32(acc[mt][1], av[mt], bv[0][2], bv[0][3]);               \
                mma_tf32(acc[mt][2], av[mt], bv[1][0], bv[1][1]);               \
                mma_tf32(acc[mt][3], av[mt], bv[1][2], bv[1][3]);               \
            }                                                                   \
        } }

    // prologue: 2 tiles in flight
    ISSUE(0, 0); asm volatile("cp.async.commit_group;");
    ISSUE(1, 1); asm volatile("cp.async.commit_group;");

    for (int kt = 0; kt < NT; ++kt) {
        int pre = kt + 2;
        if (pre < NT) { ISSUE(pre, pre % 3); }
        asm volatile("cp.async.commit_group;");   // always one group per iter
        asm volatile("cp.async.wait_group 2;");   // tile kt guaranteed complete
        __syncthreads();
        COMPUTE(kt % 3);
        __syncthreads();
    }

    // epilogue: out = acc + bias + wavelet
    const int rbase = mb * 64 + wm * 32 + (lane >> 2);
    const int cbase = nb * 64 + wn * 32 + (lane & 3) * 2;
#pragma unroll
    for (int mt = 0; mt < 2; ++mt) {
#pragma unroll
        for (int nt = 0; nt < 4; ++nt) {
            int gn = cbase + nt * 8;
            float2 bb = *reinterpret_cast<const float2*>(bias + gn);
            int gm0 = rbase + mt * 16;
            {
                const float2 wv = *reinterpret_cast<const float2*>(g_wav + (size_t)gm0 * 4096 + gn);
                float2 o;
                o.x = acc[mt][nt][0] + bb.x + wv.x;
                o.y = acc[mt][nt][1] + bb.y + wv.y;
                *reinterpret_cast<float2*>(out + (size_t)gm0 * 4096 + gn) = o;
            }
            {
                int gm1 = gm0 + 8;
                const float2 wv = *reinterpret_cast<const float2*>(g_wav + (size_t)gm1 * 4096 + gn);
                float2 o;
                o.x = acc[mt][nt][2] + bb.x + wv.x;
                o.y = acc[mt][nt][3] + bb.y + wv.y;
                *reinterpret_cast<float2*>(out + (size_t)gm1 * 4096 + gn) = o;
            }
        }
    }
#undef ISSUE
#undef COMPUTE
}

// ---------------------------------------------------------------------------
// Launch
// ---------------------------------------------------------------------------
extern "C" void kernel_launch(void* const* d_in, const int* in_sizes, int n_in,
                              void* d_out, int out_size)
{
    const float* x    = (const float*)d_in[0];   // [128, 4096]
    const float* Wt   = (const float*)d_in[1];   // [4096, 4096]
    const float* bias = (const float*)d_in[2];   // [4096]
    const float* sf   = (const float*)d_in[3];   // [4, 4]
    float* out = (float*)d_out;                  // [128, 4096]

    (void)in_sizes; (void)n_in; (void)out_size;

    wavelet_kernel<<<128, 128>>>(x, sf);

    const int smemBytes = STAGES * 2048 * 2 * (int)sizeof(float);  // 49152
    cudaFuncSetAttribute(gemm_tf32_kernel,
                         cudaFuncAttributeMaxDynamicSharedMemorySize, smemBytes);
    dim3 grid(64, 2);
    gemm_tf32_kernel<<<grid, 128, smemBytes>>>(x, Wt, bias, out);
}

// round 4
// speedup vs baseline: 2.0844x; 2.0844x over previous
#include <cuda_runtime.h>
#include <cstdint>

// ============================================================================
// WaveletKAN: out[128,4096] = x @ W^T + wavelet(x) + bias
//   Kernel 1: tf32 mma.sync GEMM, split-K=2, BM64 x BN64 x BK64, 3-stage
//             cp.async, swizzled smem + ldmatrix. 256 CTAs -> 2 CTAs/SM.
//             Writes partial sums to g_part[2].
//   Kernel 2: fused epilogue: per-image Haar DWT(4)+quantile prune+IDWT
//             (warp-bitonic sort) then out = p0 + p1 + bias + wavelet.
// ============================================================================

#define KDIM   4096
#define SK     2
#define KHALF  (KDIM / SK)        // 2048
#define BK     64
#define NT2    (KHALF / BK)       // 32
#define STAGES 3

__device__ float g_part[SK * 128 * 4096];   // split-K partials (4 MB)

// ---------------------------------------------------------------------------
// GEMM helpers
// ---------------------------------------------------------------------------
__device__ __forceinline__ void cp_async16(uint32_t dst, const void* src) {
    asm volatile("cp.async.cg.shared.global [%0], [%1], 16;\n" :: "r"(dst), "l"(src));
}
__device__ __forceinline__ void ldsm_x4(uint32_t* d, uint32_t addr) {
    asm volatile("ldmatrix.sync.aligned.m8n8.x4.shared.b16 {%0,%1,%2,%3}, [%4];"
        : "=r"(d[0]), "=r"(d[1]), "=r"(d[2]), "=r"(d[3]) : "r"(addr));
}
__device__ __forceinline__ uint32_t f2tf(uint32_t v) {
    uint32_t r;
    asm("cvt.rna.tf32.f32 %0, %1;" : "=r"(r) : "f"(__uint_as_float(v)));
    return r;
}
__device__ __forceinline__ void mma_tf32(float* c, const uint32_t* a,
                                         uint32_t b0, uint32_t b1) {
    asm("mma.sync.aligned.m16n8k8.row.col.f32.tf32.tf32.f32 "
        "{%0,%1,%2,%3}, {%4,%5,%6,%7}, {%8,%9}, {%0,%1,%2,%3};"
        : "+f"(c[0]), "+f"(c[1]), "+f"(c[2]), "+f"(c[3])
        : "r"(a[0]), "r"(a[1]), "r"(a[2]), "r"(a[3]), "r"(b0), "r"(b1));
}

// ---------------------------------------------------------------------------
// tf32 GEMM, split-K=2. 128 threads (4 warps, 32x32 warptiles).
// smem: [A0 A1 A2 | B0 B1 B2], 16 KB each stage region -> 96 KB -> 2 CTAs/SM.
// ---------------------------------------------------------------------------
__global__ void __launch_bounds__(128, 2) gemm_tf32_kernel(
    const float* __restrict__ X, const float* __restrict__ Wt)
{
    extern __shared__ float smem[];

    const int tid  = threadIdx.x;
    const int lane = tid & 31, warp = tid >> 5;
    const int wm = warp >> 1, wn = warp & 1;          // 2x2 warps, 32x32 tiles
    const int nb = blockIdx.x, mb = blockIdx.y, kz = blockIdx.z;

    const float* Ag = X  + (size_t)mb * 64 * KDIM + (size_t)kz * KHALF;
    const float* Bg = Wt + (size_t)nb * 64 * KDIM + (size_t)kz * KHALF;

    const uint32_t sBase = (uint32_t)__cvta_generic_to_shared(smem);
    const uint32_t bOfs  = STAGES * 16384u;           // B region starts at 48 KB

    float acc[2][4][4];
#pragma unroll
    for (int a1 = 0; a1 < 2; ++a1)
#pragma unroll
        for (int a2 = 0; a2 < 4; ++a2)
#pragma unroll
            for (int a3 = 0; a3 < 4; ++a3) acc[a1][a2][a3] = 0.0f;

    // ldmatrix lane geometry
    const int j = lane >> 3, r = lane & 7;
    const int cja = (j >> 1);       // A: k-chunk parity
    const int cjb = (j & 1);        // B: k-chunk parity
    const uint32_t aRow0 = (uint32_t)((wm * 32 + (j & 1) * 8 + r) * 256);
    const uint32_t aRow1 = aRow0 + 16u * 256u;
    const uint32_t bRow0 = (uint32_t)((wn * 32 + (j >> 1) * 8 + r) * 256);
    const uint32_t bRow1 = bRow0 + 16u * 256u;

    // cp.async store offsets: 64 rows x 16 chunks of 16B, XOR-swizzled
#define ISSUE(kt) {                                                            \
        int stg_ = (kt) % STAGES;                                              \
        uint32_t sa_ = sBase + (uint32_t)stg_ * 16384u;                        \
        uint32_t sb_ = sa_ + bOfs;                                             \
        const float* pa_ = Ag + (size_t)(kt) * BK;                             \
        const float* pb_ = Bg + (size_t)(kt) * BK;                             \
        _Pragma("unroll")                                                      \
        for (int i_ = 0; i_ < 8; ++i_) {                                       \
            int id_ = tid + 128 * i_;                                          \
            int row_ = id_ >> 4, c_ = id_ & 15;                                \
            uint32_t off_ = (uint32_t)(row_ * 256 + ((c_ ^ (row_ & 7)) << 4)); \
            cp_async16(sa_ + off_, pa_ + (size_t)row_ * KDIM + c_ * 4);        \
            cp_async16(sb_ + off_, pb_ + (size_t)row_ * KDIM + c_ * 4);        \
        } }

#define COMPUTE(stg) {                                                         \
        uint32_t aB = sBase + (uint32_t)(stg) * 16384u;                        \
        uint32_t bB = aB + bOfs;                                               \
        _Pragma("unroll")                                                      \
        for (int s = 0; s < 8; ++s) {                                          \
            uint32_t av[2][4], bv[2][4];                                       \
            uint32_t ca = (uint32_t)((((2 * s + cja) ^ r)) << 4);              \
            uint32_t cb = (uint32_t)((((2 * s + cjb) ^ r)) << 4);              \
            ldsm_x4(av[0], aB + aRow0 + ca);                                   \
            ldsm_x4(av[1], aB + aRow1 + ca);                                   \
            ldsm_x4(bv[0], bB + bRow0 + cb);                                   \
            ldsm_x4(bv[1], bB + bRow1 + cb);                                   \
            _Pragma("unroll")                                                  \
            for (int q = 0; q < 4; ++q) {                                      \
                av[0][q] = f2tf(av[0][q]); av[1][q] = f2tf(av[1][q]);          \
                bv[0][q] = f2tf(bv[0][q]); bv[1][q] = f2tf(bv[1][q]);          \
            }                                                                  \
            _Pragma("unroll")                                                  \
            for (int mt = 0; mt < 2; ++mt) {                                   \
                mma_tf32(acc[mt][0], av[mt], bv[0][0], bv[0][1]);              \
                mma_tf32(acc[mt][1], av[mt], bv[0][2], bv[0][3]);              \
                mma_tf32(acc[mt][2], av[mt], bv[1][0], bv[1][1]);              \
                mma_tf32(acc[mt][3], av[mt], bv[1][2], bv[1][3]);              \
            }                                                                  \
        } }

    // prologue: 2 tiles in flight
    ISSUE(0); asm volatile("cp.async.commit_group;");
    ISSUE(1); asm volatile("cp.async.commit_group;");

    for (int kt = 0; kt < NT2; ++kt) {
        asm volatile("cp.async.wait_group 1;");
        __syncthreads();
        COMPUTE(kt % STAGES);
        if (kt + 2 < NT2) { ISSUE(kt + 2); }
        asm volatile("cp.async.commit_group;");
    }

    // epilogue: plain partial-sum stores
    float* P = g_part + (size_t)kz * (128 * 4096);
    const int rbase = mb * 64 + wm * 32 + (lane >> 2);
    const int cbase = nb * 64 + wn * 32 + (lane & 3) * 2;
#pragma unroll
    for (int mt = 0; mt < 2; ++mt) {
#pragma unroll
        for (int nt = 0; nt < 4; ++nt) {
            int gn  = cbase + nt * 8;
            int gm0 = rbase + mt * 16;
            float2 o0; o0.x = acc[mt][nt][0]; o0.y = acc[mt][nt][1];
            *reinterpret_cast<float2*>(P + (size_t)gm0 * 4096 + gn) = o0;
            float2 o1; o1.x = acc[mt][nt][2]; o1.y = acc[mt][nt][3];
            *reinterpret_cast<float2*>(P + (size_t)(gm0 + 8) * 4096 + gn) = o1;
        }
    }
#undef ISSUE
#undef COMPUTE
}

// ---------------------------------------------------------------------------
// Fused epilogue: wavelet (warp-bitonic quantile prune) + split-K reduce.
// One block per batch image (128 blocks), 256 threads (8 warps).
// ---------------------------------------------------------------------------
__global__ void __launch_bounds__(256) epilogue_kernel(
    const float* __restrict__ x, const float* __restrict__ sf,
    const float* __restrict__ bias, float* __restrict__ out)
{
    __shared__ float A[4096];           // 64x64 image / reconstruction
    __shared__ float Wb0[1024];
    __shared__ float Wb1[1024];
    __shared__ float lev[5440];         // 4096 + 1024 + 256 + 64

    const int b      = blockIdx.x;
    const int tid    = threadIdx.x;
    const int warpId = tid >> 5;
    const int lane   = tid & 31;
    const float* xb  = x + (size_t)b * 4096;

    for (int i = tid; i < 4096; i += 256) A[i] = xb[i];
    __syncthreads();

    const int loff[4] = {0, 4096, 5120, 5376};

    float* cur = A;
    float* nxt = Wb0;

    // ------------- forward: DWT + scale + prune -------------
#pragma unroll
    for (int l = 0; l < 4; ++l) {
        const int h = 64 >> l, hh = h >> 1;
        const float s0 = sf[l * 4 + 0], s1 = sf[l * 4 + 1];
        const float s2 = sf[l * 4 + 2], s3 = sf[l * 4 + 3];
        float* L = lev + loff[l];
        const int n = hh * hh;

        for (int idx = tid; idx < n; idx += 256) {
            int i = idx / hh, jj = idx - i * hh;
            float a  = cur[(2 * i)     * h + 2 * jj];
            float bb = cur[(2 * i)     * h + 2 * jj + 1];
            float c  = cur[(2 * i + 1) * h + 2 * jj];
            float d  = cur[(2 * i + 1) * h + 2 * jj + 1];
            float ca = (a + bb + c + d) * 0.5f;
            float ch = (a - bb + c - d) * 0.5f;
            float cv = (a + bb - c - d) * 0.5f;
            float cd = (a - bb - c + d) * 0.5f;
            nxt[idx] = ca;   // raw cA feeds next level
            L[(0 * hh + i) * hh + jj] = ca * s0;
            L[(1 * hh + i) * hh + jj] = ch * s1;
            L[(2 * hh + i) * hh + jj] = cv * s2;
            L[(3 * hh + i) * hh + jj] = cd * s3;
        }
        __syncthreads();

        // prune: per-row 0.4 quantile via warp-bitonic sort (hh lanes/row)
        {
            const int rpw = 32 / hh;          // rows packed per warp
            const int t   = lane & (hh - 1);  // local lane within row group
            const int sub = lane / hh;        // which packed row
            const int lo2  = (int)(0.4f * (float)(hh - 1));
            const float frac = 0.4f * (float)(hh - 1) - (float)lo2;
            const int gb = lane & ~(hh - 1);  // group base lane

            for (int base = warpId * rpw; base < 4 * hh; base += 8 * rpw) {
                int row = base + sub;
                float* rp = L + row * hh;
                float orig = rp[t];
                float v = fabsf(orig);
                // bitonic sort ascending within hh-lane groups
#pragma unroll
                for (int k = 2; k <= hh; k <<= 1) {
#pragma unroll
                    for (int jstep = k >> 1; jstep > 0; jstep >>= 1) {
                        float o = __shfl_xor_sync(0xffffffffu, v, jstep);
                        bool keepMin = (((t & k) == 0) == ((t & jstep) == 0));
                        v = keepMin ? fminf(v, o) : fmaxf(v, o);
                    }
                }
                float vlo = __shfl_sync(0xffffffffu, v, gb + lo2);
                float vhi = __shfl_sync(0xffffffffu, v, gb + lo2 + 1);
                float thr = vlo + frac * (vhi - vlo);
                rp[t] = (fabsf(orig) > thr) ? orig : 0.0f;
            }
        }
        __syncthreads();

        float* newcur = nxt;
        nxt = (newcur == Wb0) ? Wb1 : Wb0;
        cur = newcur;
    }

    // ------------- reconstruction -------------
    __syncthreads();
    if (tid < 16) Wb0[tid] = lev[5376 + tid];   // pruned+scaled cA of level 3
    __syncthreads();

    cur = Wb0;
#pragma unroll
    for (int l = 3; l >= 0; --l) {
        const int hh = 32 >> l, h2 = 2 * hh;
        const int n = hh * hh;
        float* L = lev + loff[l];
        float* outb = (l == 0) ? A : ((cur == Wb0) ? Wb1 : Wb0);

        for (int idx = tid; idx < n; idx += 256) {
            int i = idx / hh, jj = idx - i * hh;
            float ca = cur[idx];
            float ch = L[(1 * hh + i) * hh + jj];
            float cv = L[(2 * hh + i) * hh + jj];
            float cd = L[(3 * hh + i) * hh + jj];
            float a  = (ca + ch + cv + cd) * 0.5f;
            float bb = (ca - ch + cv - cd) * 0.5f;
            float c  = (ca + ch - cv - cd) * 0.5f;
            float d  = (ca - ch - cv + cd) * 0.5f;
            outb[(2 * i)     * h2 + 2 * jj]     = a;
            outb[(2 * i)     * h2 + 2 * jj + 1] = bb;
            outb[(2 * i + 1) * h2 + 2 * jj]     = c;
            outb[(2 * i + 1) * h2 + 2 * jj + 1] = d;
        }
        __syncthreads();
        cur = outb;
    }

    // ------------- reduce: out = p0 + p1 + bias + wavelet -------------
    const float4* P0 = reinterpret_cast<const float4*>(g_part + (size_t)b * 4096);
    const float4* P1 = reinterpret_cast<const float4*>(g_part + (size_t)(128 + b) * 4096);
    const float4* Bv = reinterpret_cast<const float4*>(bias);
    const float4* Av = reinterpret_cast<const float4*>(A);
    float4* O  = reinterpret_cast<float4*>(out + (size_t)b * 4096);
    for (int i = tid; i < 1024; i += 256) {
        float4 p0 = P0[i], p1 = P1[i], bb = Bv[i], wv = Av[i];
        float4 o;
        o.x = p0.x + p1.x + bb.x + wv.x;
        o.y = p0.y + p1.y + bb.y + wv.y;
        o.z = p0.z + p1.z + bb.z + wv.z;
        o.w = p0.w + p1.w + bb.w + wv.w;
        O[i] = o;
    }
}

// ---------------------------------------------------------------------------
// Launch
// ---------------------------------------------------------------------------
extern "C" void kernel_launch(void* const* d_in, const int* in_sizes, int n_in,
                              void* d_out, int out_size)
{
    const float* x    = (const float*)d_in[0];   // [128, 4096]
    const float* Wt   = (const float*)d_in[1];   // [4096, 4096]
    const float* bias = (const float*)d_in[2];   // [4096]
    const float* sf   = (const float*)d_in[3];   // [4, 4]
    float* out = (float*)d_out;                  // [128, 4096]

    (void)in_sizes; (void)n_in; (void)out_size;

    const int smemBytes = STAGES * 16384 * 2;    // 96 KB
    cudaFuncSetAttribute(gemm_tf32_kernel,
                         cudaFuncAttributeMaxDynamicSharedMemorySize, smemBytes);

    dim3 grid(64, 2, SK);
    gemm_tf32_kernel<<<grid, 128, smemBytes>>>(x, Wt);
    epilogue_kernel<<<128, 256>>>(x, sf, bias, out);
}